// round 1
// baseline (speedup 1.0000x reference)
#include <cuda_runtime.h>
#include <math.h>

#define N_NODES 50000
#define N_EDGES 800000
#define DIM     128
#define HEADS   8
#define GRAPHS  64
#define NCLASS  10
#define SLOPE   0.2f
#define BN_EPS  1e-5f

// ---------------- scratch (device globals; no allocation allowed) ----------
__device__ float g_h1[N_NODES * DIM];        // layer1 h, later reused for layer2 h2pre
__device__ float g_out1[N_NODES * DIM];      // layer1 out -> hmid (in place), later layer2 out
__device__ float g_asrc1[N_NODES * HEADS];
__device__ float g_adst1[N_NODES * HEADS];
__device__ float g_m1[N_NODES * HEADS];
__device__ float g_den1[N_NODES * HEADS];
__device__ float g_selfex1[N_NODES * HEADS];
__device__ float g_ex1[N_EDGES * HEADS];
__device__ float g_asrc2[N_NODES];
__device__ float g_adst2[N_NODES];
__device__ float g_m2[N_NODES];
__device__ float g_den2[N_NODES];
__device__ float g_selfex2[N_NODES];
__device__ float g_ex2[N_EDGES];
__device__ float g_gsum[GRAPHS * DIM];
__device__ float g_gcnt[GRAPHS];

// ---------------- helpers ---------------------------------------------------
__device__ __forceinline__ float leaky(float x) { return x > 0.f ? x : SLOPE * x; }

__device__ __forceinline__ void atomicMaxFloat(float* addr, float v) {
    // order-preserving trick: non-negative floats compare as signed int,
    // negative floats compare reversed as unsigned int.
    if (v >= 0.f) atomicMax((int*)addr, __float_as_int(v));
    else          atomicMin((unsigned int*)addr, __float_as_uint(v));
}

// ---------------- GEMM (h = X @ W) fused with alpha reductions --------------
// one warp per node row; each lane owns 4 output columns (float4 loads of W).
__global__ void gemm_alpha_kernel(const float* __restrict__ X,
                                  const float* __restrict__ W,
                                  const float* __restrict__ attS,
                                  const float* __restrict__ attD,
                                  float* __restrict__ Hout,
                                  float* __restrict__ aS,
                                  float* __restrict__ aD,
                                  int heads)
{
    __shared__ float xs[4][DIM];
    int w    = threadIdx.x >> 5;
    int lane = threadIdx.x & 31;
    int row  = blockIdx.x * 4 + w;
    if (row >= N_NODES) return;

    float4 xv = ((const float4*)(X + (long)row * DIM))[lane];
    ((float4*)xs[w])[lane] = xv;
    __syncwarp();

    const float4* W4 = (const float4*)W;
    float4 acc = make_float4(0.f, 0.f, 0.f, 0.f);
#pragma unroll
    for (int k = 0; k < DIM; k++) {
        float  xk = xs[w][k];
        float4 wv = W4[k * 32 + lane];
        acc.x = fmaf(xk, wv.x, acc.x);
        acc.y = fmaf(xk, wv.y, acc.y);
        acc.z = fmaf(xk, wv.z, acc.z);
        acc.w = fmaf(xk, wv.w, acc.w);
    }
    ((float4*)(Hout + (long)row * DIM))[lane] = acc;

    float4 sv = ((const float4*)attS)[lane];
    float4 dv = ((const float4*)attD)[lane];
    float ps = acc.x * sv.x + acc.y * sv.y + acc.z * sv.z + acc.w * sv.w;
    float pd = acc.x * dv.x + acc.y * dv.y + acc.z * dv.z + acc.w * dv.w;
    // reduce within groups of 4 lanes (one head = 16 channels = 4 lanes)
    ps += __shfl_xor_sync(0xffffffff, ps, 1);
    ps += __shfl_xor_sync(0xffffffff, ps, 2);
    pd += __shfl_xor_sync(0xffffffff, pd, 1);
    pd += __shfl_xor_sync(0xffffffff, pd, 2);
    if (heads == 1) {
        ps += __shfl_xor_sync(0xffffffff, ps, 4);
        ps += __shfl_xor_sync(0xffffffff, ps, 8);
        ps += __shfl_xor_sync(0xffffffff, ps, 16);
        pd += __shfl_xor_sync(0xffffffff, pd, 4);
        pd += __shfl_xor_sync(0xffffffff, pd, 8);
        pd += __shfl_xor_sync(0xffffffff, pd, 16);
        if (lane == 0) { aS[row] = ps; aD[row] = pd; }
    } else {
        if ((lane & 3) == 0) {
            aS[row * HEADS + (lane >> 2)] = ps;
            aD[row * HEADS + (lane >> 2)] = pd;
        }
    }
}

// ---------------- softmax passes --------------------------------------------
// init max with the self-loop edge score (every node has one)
__global__ void self_init_max(const float* __restrict__ aS, const float* __restrict__ aD,
                              float* __restrict__ m, int n)
{
    int i = blockIdx.x * blockDim.x + threadIdx.x;
    if (i < n) m[i] = leaky(aS[i] + aD[i]);
}

__global__ void edge_max8(const int* __restrict__ src, const int* __restrict__ dst,
                          const float* __restrict__ aS, const float* __restrict__ aD,
                          float* __restrict__ m)
{
    int e = blockIdx.x * blockDim.x + threadIdx.x;
    if (e >= N_EDGES) return;
    int s = src[e], d = dst[e];
    const float4* S4 = (const float4*)(aS + (long)s * HEADS);
    const float4* D4 = (const float4*)(aD + (long)d * HEADS);
#pragma unroll
    for (int q = 0; q < 2; q++) {
        float4 a = S4[q], b = D4[q];
        float v0 = leaky(a.x + b.x), v1 = leaky(a.y + b.y);
        float v2 = leaky(a.z + b.z), v3 = leaky(a.w + b.w);
        atomicMaxFloat(&m[(long)d * HEADS + q * 4 + 0], v0);
        atomicMaxFloat(&m[(long)d * HEADS + q * 4 + 1], v1);
        atomicMaxFloat(&m[(long)d * HEADS + q * 4 + 2], v2);
        atomicMaxFloat(&m[(long)d * HEADS + q * 4 + 3], v3);
    }
}

__global__ void edge_max1(const int* __restrict__ src, const int* __restrict__ dst,
                          const float* __restrict__ aS, const float* __restrict__ aD,
                          float* __restrict__ m)
{
    int e = blockIdx.x * blockDim.x + threadIdx.x;
    if (e >= N_EDGES) return;
    int s = src[e], d = dst[e];
    atomicMaxFloat(&m[d], leaky(aS[s] + aD[d]));
}

__global__ void self_exp(const float* __restrict__ aS, const float* __restrict__ aD,
                         const float* __restrict__ m, float* __restrict__ selfex,
                         float* __restrict__ den, int n)
{
    int i = blockIdx.x * blockDim.x + threadIdx.x;
    if (i < n) {
        float ex = __expf(leaky(aS[i] + aD[i]) - m[i]);
        selfex[i] = ex;
        den[i]    = ex;   // self contribution initializes denominator
    }
}

__global__ void edge_exp8(const int* __restrict__ src, const int* __restrict__ dst,
                          const float* __restrict__ aS, const float* __restrict__ aD,
                          const float* __restrict__ m, float* __restrict__ exbuf,
                          float* __restrict__ den)
{
    int e = blockIdx.x * blockDim.x + threadIdx.x;
    if (e >= N_EDGES) return;
    int s = src[e], d = dst[e];
    const float4* S4 = (const float4*)(aS + (long)s * HEADS);
    const float4* D4 = (const float4*)(aD + (long)d * HEADS);
    const float4* M4 = (const float4*)(m  + (long)d * HEADS);
#pragma unroll
    for (int q = 0; q < 2; q++) {
        float4 a = S4[q], b = D4[q], mm = M4[q];
        float4 exv;
        exv.x = __expf(leaky(a.x + b.x) - mm.x);
        exv.y = __expf(leaky(a.y + b.y) - mm.y);
        exv.z = __expf(leaky(a.z + b.z) - mm.z);
        exv.w = __expf(leaky(a.w + b.w) - mm.w);
        ((float4*)exbuf)[(long)e * 2 + q] = exv;
        atomicAdd(&den[(long)d * HEADS + q * 4 + 0], exv.x);
        atomicAdd(&den[(long)d * HEADS + q * 4 + 1], exv.y);
        atomicAdd(&den[(long)d * HEADS + q * 4 + 2], exv.z);
        atomicAdd(&den[(long)d * HEADS + q * 4 + 3], exv.w);
    }
}

__global__ void edge_exp1(const int* __restrict__ src, const int* __restrict__ dst,
                          const float* __restrict__ aS, const float* __restrict__ aD,
                          const float* __restrict__ m, float* __restrict__ exbuf,
                          float* __restrict__ den)
{
    int e = blockIdx.x * blockDim.x + threadIdx.x;
    if (e >= N_EDGES) return;
    int s = src[e], d = dst[e];
    float ex = __expf(leaky(aS[s] + aD[d]) - m[d]);
    exbuf[e] = ex;
    atomicAdd(&den[d], ex);
}

// ---------------- message aggregation ---------------------------------------
// self message initializes out (plain store)
__global__ void self_msg(const float* __restrict__ H, const float* __restrict__ selfex,
                         const float* __restrict__ den, float* __restrict__ out, int heads)
{
    int i = blockIdx.x * blockDim.x + threadIdx.x;
    if (i >= N_NODES * 32) return;
    int n = i >> 5, q = i & 31;
    int h = (heads == HEADS) ? (q >> 2) : 0;
    float alpha = selfex[(long)n * heads + h] / den[(long)n * heads + h];
    float4 hv = ((const float4*)H)[(long)n * 32 + q];
    float4 o  = make_float4(hv.x * alpha, hv.y * alpha, hv.z * alpha, hv.w * alpha);
    ((float4*)out)[(long)n * 32 + q] = o;
}

// one warp per edge: 32 lanes x float4 covers 128 channels
__global__ void edge_msg(const int* __restrict__ src, const int* __restrict__ dst,
                         const float* __restrict__ H, const float* __restrict__ exbuf,
                         const float* __restrict__ den, float* __restrict__ out, int heads)
{
    int gw   = (blockIdx.x * blockDim.x + threadIdx.x) >> 5;
    int lane = threadIdx.x & 31;
    if (gw >= N_EDGES) return;
    int s = src[gw], d = dst[gw];
    int h = (heads == HEADS) ? (lane >> 2) : 0;
    float alpha = exbuf[(long)gw * heads + h] / den[(long)d * heads + h];
    float4 hv = ((const float4*)H)[(long)s * 32 + lane];
    float* o = out + (long)d * DIM + lane * 4;
    atomicAdd(o + 0, hv.x * alpha);
    atomicAdd(o + 1, hv.y * alpha);
    atomicAdd(o + 2, hv.z * alpha);
    atomicAdd(o + 3, hv.w * alpha);
}

// ---------------- BN(eval) + ELU (in place, adds bias b1 first) --------------
__global__ void bn_elu(float* __restrict__ data, const float* __restrict__ b,
                       const float* __restrict__ g, const float* __restrict__ beta,
                       const float* __restrict__ mu, const float* __restrict__ var)
{
    int i = blockIdx.x * blockDim.x + threadIdx.x;
    if (i >= N_NODES * DIM) return;
    int d = i & (DIM - 1);
    float v = data[i] + b[d];
    v = (v - mu[d]) * g[d] * rsqrtf(var[d] + BN_EPS) + beta[d];
    data[i] = v > 0.f ? v : expm1f(v);
}

// ---------------- pooling ----------------------------------------------------
__global__ void zero_pool(float* __restrict__ gsum, float* __restrict__ gcnt)
{
    int i = blockIdx.x * blockDim.x + threadIdx.x;
    if (i < GRAPHS * DIM) gsum[i] = 0.f;
    if (i < GRAPHS) gcnt[i] = 0.f;
}

__global__ void pool_sum(const float* __restrict__ out2, const float* __restrict__ b2,
                         const int* __restrict__ batch, float* __restrict__ gsum)
{
    int i = blockIdx.x * blockDim.x + threadIdx.x;
    if (i >= N_NODES * DIM) return;
    int n = i >> 7, d = i & (DIM - 1);
    atomicAdd(&gsum[(long)batch[n] * DIM + d], out2[i] + b2[d]);
}

__global__ void pool_cnt(const int* __restrict__ batch, float* __restrict__ gcnt)
{
    int i = blockIdx.x * blockDim.x + threadIdx.x;
    if (i < N_NODES) atomicAdd(&gcnt[batch[i]], 1.f);
}

// ---------------- classifier MLP ----------------------------------------------
__global__ void classifier(const float* __restrict__ gsum, const float* __restrict__ gcnt,
                           const float* __restrict__ Wc1, const float* __restrict__ bc1,
                           const float* __restrict__ Wc2, const float* __restrict__ bc2,
                           float* __restrict__ out)
{
    __shared__ float emb[DIM];
    __shared__ float z[64];
    int g = blockIdx.x, t = threadIdx.x;
    float cnt = fmaxf(gcnt[g], 1.f);
    emb[t] = gsum[(long)g * DIM + t] / cnt;
    __syncthreads();
    if (t < 64) {
        float a = bc1[t];
#pragma unroll 8
        for (int k = 0; k < DIM; k++) a = fmaf(emb[k], Wc1[k * 64 + t], a);
        z[t] = a > 0.f ? a : expm1f(a);
    }
    __syncthreads();
    if (t < NCLASS) {
        float a = bc2[t];
#pragma unroll
        for (int k = 0; k < 64; k++) a = fmaf(z[k], Wc2[k * NCLASS + t], a);
        out[(long)g * NCLASS + t] = a;
    }
}

// ---------------- launch ------------------------------------------------------
extern "C" void kernel_launch(void* const* d_in, const int* in_sizes, int n_in,
                              void* d_out, int out_size)
{
    const float* x        = (const float*)d_in[0];
    const int*   esrc     = (const int*)  d_in[1];
    const int*   edst     = (const int*)  d_in[2];
    const int*   batch    = (const int*)  d_in[3];
    const float* W1       = (const float*)d_in[4];
    const float* b1       = (const float*)d_in[5];
    const float* att_src1 = (const float*)d_in[6];
    const float* att_dst1 = (const float*)d_in[7];
    const float* W2       = (const float*)d_in[8];
    const float* b2       = (const float*)d_in[9];
    const float* att_src2 = (const float*)d_in[10];
    const float* att_dst2 = (const float*)d_in[11];
    const float* bn_g     = (const float*)d_in[12];
    const float* bn_b     = (const float*)d_in[13];
    const float* bn_m     = (const float*)d_in[14];
    const float* bn_v     = (const float*)d_in[15];
    const float* Wc1      = (const float*)d_in[16];
    const float* bc1      = (const float*)d_in[17];
    const float* Wc2      = (const float*)d_in[18];
    const float* bc2      = (const float*)d_in[19];
    float* out = (float*)d_out;

    float *p_h1, *p_out1, *p_asrc1, *p_adst1, *p_m1, *p_den1, *p_selfex1, *p_ex1;
    float *p_asrc2, *p_adst2, *p_m2, *p_den2, *p_selfex2, *p_ex2, *p_gsum, *p_gcnt;
    cudaGetSymbolAddress((void**)&p_h1,      g_h1);
    cudaGetSymbolAddress((void**)&p_out1,    g_out1);
    cudaGetSymbolAddress((void**)&p_asrc1,   g_asrc1);
    cudaGetSymbolAddress((void**)&p_adst1,   g_adst1);
    cudaGetSymbolAddress((void**)&p_m1,      g_m1);
    cudaGetSymbolAddress((void**)&p_den1,    g_den1);
    cudaGetSymbolAddress((void**)&p_selfex1, g_selfex1);
    cudaGetSymbolAddress((void**)&p_ex1,     g_ex1);
    cudaGetSymbolAddress((void**)&p_asrc2,   g_asrc2);
    cudaGetSymbolAddress((void**)&p_adst2,   g_adst2);
    cudaGetSymbolAddress((void**)&p_m2,      g_m2);
    cudaGetSymbolAddress((void**)&p_den2,    g_den2);
    cudaGetSymbolAddress((void**)&p_selfex2, g_selfex2);
    cudaGetSymbolAddress((void**)&p_ex2,     g_ex2);
    cudaGetSymbolAddress((void**)&p_gsum,    g_gsum);
    cudaGetSymbolAddress((void**)&p_gcnt,    g_gcnt);

    const int TB = 256;
    int gemm_blocks  = (N_NODES + 3) / 4;
    int nodeH_blocks = (N_NODES * HEADS + TB - 1) / TB;
    int node_blocks  = (N_NODES + TB - 1) / TB;
    int edge_blocks  = (N_EDGES + TB - 1) / TB;
    int msg_blocks   = (N_EDGES * 32 + TB - 1) / TB;
    int n32_blocks   = (N_NODES * 32 + TB - 1) / TB;
    int nd_blocks    = (N_NODES * DIM + TB - 1) / TB;

    // -------- layer 1 (HEADS=8, concat) --------
    gemm_alpha_kernel<<<gemm_blocks, 128>>>(x, W1, att_src1, att_dst1, p_h1, p_asrc1, p_adst1, HEADS);
    self_init_max<<<nodeH_blocks, TB>>>(p_asrc1, p_adst1, p_m1, N_NODES * HEADS);
    edge_max8<<<edge_blocks, TB>>>(esrc, edst, p_asrc1, p_adst1, p_m1);
    self_exp<<<nodeH_blocks, TB>>>(p_asrc1, p_adst1, p_m1, p_selfex1, p_den1, N_NODES * HEADS);
    edge_exp8<<<edge_blocks, TB>>>(esrc, edst, p_asrc1, p_adst1, p_m1, p_ex1, p_den1);
    self_msg<<<n32_blocks, TB>>>(p_h1, p_selfex1, p_den1, p_out1, HEADS);
    edge_msg<<<msg_blocks, TB>>>(esrc, edst, p_h1, p_ex1, p_den1, p_out1, HEADS);
    bn_elu<<<nd_blocks, TB>>>(p_out1, b1, bn_g, bn_b, bn_m, bn_v);

    // -------- layer 2 (heads=1, mean == identity) --------
    gemm_alpha_kernel<<<gemm_blocks, 128>>>(p_out1, W2, att_src2, att_dst2, p_h1, p_asrc2, p_adst2, 1);
    self_init_max<<<node_blocks, TB>>>(p_asrc2, p_adst2, p_m2, N_NODES);
    edge_max1<<<edge_blocks, TB>>>(esrc, edst, p_asrc2, p_adst2, p_m2);
    self_exp<<<node_blocks, TB>>>(p_asrc2, p_adst2, p_m2, p_selfex2, p_den2, N_NODES);
    edge_exp1<<<edge_blocks, TB>>>(esrc, edst, p_asrc2, p_adst2, p_m2, p_ex2, p_den2);
    self_msg<<<n32_blocks, TB>>>(p_h1, p_selfex2, p_den2, p_out1, 1);
    edge_msg<<<msg_blocks, TB>>>(esrc, edst, p_h1, p_ex2, p_den2, p_out1, 1);

    // -------- pool + classifier --------
    zero_pool<<<(GRAPHS * DIM + TB - 1) / TB, TB>>>(p_gsum, p_gcnt);
    pool_sum<<<nd_blocks, TB>>>(p_out1, b2, batch, p_gsum);
    pool_cnt<<<node_blocks, TB>>>(batch, p_gcnt);
    classifier<<<GRAPHS, DIM>>>(p_gsum, p_gcnt, Wc1, bc1, Wc2, bc2, out);
}

// round 2
// speedup vs baseline: 2.0264x; 2.0264x over previous
#include <cuda_runtime.h>
#include <math.h>

#define N_NODES 50000
#define N_EDGES 800000
#define DIM     128
#define HEADS   8
#define GRAPHS  64
#define NCLASS  10
#define SLOPE   0.2f
#define BN_EPS  1e-5f

// ---------------- scratch (device globals) ----------------------------------
__device__ float g_h[N_NODES * DIM];        // h = X@W (per layer)
__device__ float g_mid[N_NODES * DIM];      // layer1 output after BN+ELU
__device__ float g_asrc[N_NODES * HEADS];
__device__ float g_adst[N_NODES * HEADS];
__device__ int   g_deg[N_NODES];
__device__ int   g_off[N_NODES + 1];
__device__ int   g_cur[N_NODES];
__device__ int   g_eid[N_EDGES];
__device__ float g_gsum[GRAPHS * DIM];
__device__ float g_gcnt[GRAPHS];

__device__ __forceinline__ float leaky(float x) { return x > 0.f ? x : SLOPE * x; }

// ---------------- CSR build --------------------------------------------------
__global__ void zero_all(int* __restrict__ deg, float* __restrict__ gsum,
                         float* __restrict__ gcnt)
{
    int i = blockIdx.x * blockDim.x + threadIdx.x;
    if (i < N_NODES) deg[i] = 0;
    if (i < GRAPHS * DIM) gsum[i] = 0.f;
    if (i < GRAPHS) gcnt[i] = 0.f;
}

__global__ void hist_dst(const int* __restrict__ dst, int* __restrict__ deg)
{
    int e = blockIdx.x * blockDim.x + threadIdx.x;
    if (e < N_EDGES) atomicAdd(&deg[dst[e]], 1);
}

__global__ void scan_deg(const int* __restrict__ deg, int* __restrict__ off,
                         int* __restrict__ cur)
{
    __shared__ int s[1024];
    int t = threadIdx.x;
    const int R = (N_NODES + 1023) / 1024;
    int base = t * R;
    int sum = 0;
    for (int i = 0; i < R; i++) {
        int idx = base + i;
        if (idx < N_NODES) sum += deg[idx];
    }
    s[t] = sum;
    __syncthreads();
    for (int d = 1; d < 1024; d <<= 1) {
        int u = (t >= d) ? s[t - d] : 0;
        __syncthreads();
        s[t] += u;
        __syncthreads();
    }
    int run = s[t] - sum;  // exclusive prefix of this thread's range
    for (int i = 0; i < R; i++) {
        int idx = base + i;
        if (idx < N_NODES) {
            off[idx] = run;
            cur[idx] = run;
            run += deg[idx];
        }
    }
    if (t == 0) off[N_NODES] = N_EDGES;
}

__global__ void scatter_edges(const int* __restrict__ dst, int* __restrict__ cur,
                              int* __restrict__ eid)
{
    int e = blockIdx.x * blockDim.x + threadIdx.x;
    if (e < N_EDGES) {
        int pos = atomicAdd(&cur[dst[e]], 1);
        eid[pos] = e;
    }
}

// ---------------- GEMM (h = X @ W) fused with alpha reductions --------------
__global__ void gemm_alpha_kernel(const float* __restrict__ X,
                                  const float* __restrict__ W,
                                  const float* __restrict__ attS,
                                  const float* __restrict__ attD,
                                  float* __restrict__ Hout,
                                  float* __restrict__ aS,
                                  float* __restrict__ aD,
                                  int heads)
{
    __shared__ float xs[4][DIM];
    int w    = threadIdx.x >> 5;
    int lane = threadIdx.x & 31;
    int row  = blockIdx.x * 4 + w;
    if (row >= N_NODES) return;

    float4 xv = ((const float4*)(X + (long)row * DIM))[lane];
    ((float4*)xs[w])[lane] = xv;
    __syncwarp();

    const float4* W4 = (const float4*)W;
    float4 acc = make_float4(0.f, 0.f, 0.f, 0.f);
#pragma unroll
    for (int k = 0; k < DIM; k++) {
        float  xk = xs[w][k];
        float4 wv = W4[k * 32 + lane];
        acc.x = fmaf(xk, wv.x, acc.x);
        acc.y = fmaf(xk, wv.y, acc.y);
        acc.z = fmaf(xk, wv.z, acc.z);
        acc.w = fmaf(xk, wv.w, acc.w);
    }
    ((float4*)(Hout + (long)row * DIM))[lane] = acc;

    float4 sv = ((const float4*)attS)[lane];
    float4 dv = ((const float4*)attD)[lane];
    float ps = acc.x * sv.x + acc.y * sv.y + acc.z * sv.z + acc.w * sv.w;
    float pd = acc.x * dv.x + acc.y * dv.y + acc.z * dv.z + acc.w * dv.w;
    ps += __shfl_xor_sync(0xffffffff, ps, 1);
    ps += __shfl_xor_sync(0xffffffff, ps, 2);
    pd += __shfl_xor_sync(0xffffffff, pd, 1);
    pd += __shfl_xor_sync(0xffffffff, pd, 2);
    if (heads == 1) {
        ps += __shfl_xor_sync(0xffffffff, ps, 4);
        ps += __shfl_xor_sync(0xffffffff, ps, 8);
        ps += __shfl_xor_sync(0xffffffff, ps, 16);
        pd += __shfl_xor_sync(0xffffffff, pd, 4);
        pd += __shfl_xor_sync(0xffffffff, pd, 8);
        pd += __shfl_xor_sync(0xffffffff, pd, 16);
        if (lane == 0) { aS[row] = ps; aD[row] = pd; }
    } else {
        if ((lane & 3) == 0) {
            aS[row * HEADS + (lane >> 2)] = ps;
            aD[row * HEADS + (lane >> 2)] = pd;
        }
    }
}

// ---------------- layer 1 fused aggregation (+bias+BN+ELU) ------------------
// one warp per destination node; CSR in-edges; self loop analytic.
__global__ void agg_layer1(const int* __restrict__ eid, const int* __restrict__ off,
                           const int* __restrict__ src,
                           const float* __restrict__ aS, const float* __restrict__ aD,
                           const float* __restrict__ H,
                           const float* __restrict__ b1,
                           const float* __restrict__ bn_g, const float* __restrict__ bn_b,
                           const float* __restrict__ bn_m, const float* __restrict__ bn_v,
                           float* __restrict__ out)
{
    int node = blockIdx.x * 8 + (threadIdx.x >> 5);
    if (node >= N_NODES) return;
    int lane = threadIdx.x & 31;
    int h8   = lane & 7;       // head this lane tracks for softmax stats
    int head = lane >> 2;      // head of this lane's 4 output channels

    float aD_h    = aD[(long)node * HEADS + h8];
    float selfv   = leaky(aS[(long)node * HEADS + h8] + aD_h);
    int beg = off[node], end = off[node + 1];

    // pass 1: max (4 edges per iteration)
    float m = selfv;
    for (int i = beg + (lane >> 3); i < end; i += 4) {
        int s = src[eid[i]];
        m = fmaxf(m, leaky(aS[(long)s * HEADS + h8] + aD_h));
    }
    m = fmaxf(m, __shfl_xor_sync(0xffffffff, m, 8));
    m = fmaxf(m, __shfl_xor_sync(0xffffffff, m, 16));

    float den = __expf(selfv - m);                 // self contribution
    float ex_self = __shfl_sync(0xffffffff, den, head);
    float4 hv = ((const float4*)H)[(long)node * 32 + lane];
    float4 acc = make_float4(hv.x * ex_self, hv.y * ex_self,
                             hv.z * ex_self, hv.w * ex_self);

    // pass 2: exp + weighted gather
    for (int i = beg; i < end; i++) {
        int s = src[eid[i]];
        float ex = __expf(leaky(aS[(long)s * HEADS + h8] + aD_h) - m);
        den += ex;
        float exh = __shfl_sync(0xffffffff, ex, head);
        float4 hs = ((const float4*)H)[(long)s * 32 + lane];
        acc.x = fmaf(hs.x, exh, acc.x);
        acc.y = fmaf(hs.y, exh, acc.y);
        acc.z = fmaf(hs.z, exh, acc.z);
        acc.w = fmaf(hs.w, exh, acc.w);
    }
    float inv = 1.f / __shfl_sync(0xffffffff, den, head);

    // epilogue: + b1, BN(eval), ELU
    float4 bb = ((const float4*)b1)[lane];
    float4 gg = ((const float4*)bn_g)[lane];
    float4 be = ((const float4*)bn_b)[lane];
    float4 mu = ((const float4*)bn_m)[lane];
    float4 va = ((const float4*)bn_v)[lane];
    float4 o;
    o.x = (acc.x * inv + bb.x - mu.x) * gg.x * rsqrtf(va.x + BN_EPS) + be.x;
    o.y = (acc.y * inv + bb.y - mu.y) * gg.y * rsqrtf(va.y + BN_EPS) + be.y;
    o.z = (acc.z * inv + bb.z - mu.z) * gg.z * rsqrtf(va.z + BN_EPS) + be.z;
    o.w = (acc.w * inv + bb.w - mu.w) * gg.w * rsqrtf(va.w + BN_EPS) + be.w;
    o.x = o.x > 0.f ? o.x : expm1f(o.x);
    o.y = o.y > 0.f ? o.y : expm1f(o.y);
    o.z = o.z > 0.f ? o.z : expm1f(o.z);
    o.w = o.w > 0.f ? o.w : expm1f(o.w);
    ((float4*)out)[(long)node * 32 + lane] = o;
}

// ---------------- layer 2 fused aggregation (+pool) -------------------------
// heads=1. Output written only into graph pooling sums (b2 added post-pool).
__global__ void agg_layer2(const int* __restrict__ eid, const int* __restrict__ off,
                           const int* __restrict__ src,
                           const float* __restrict__ aS, const float* __restrict__ aD,
                           const float* __restrict__ H,
                           const int* __restrict__ batch,
                           float* __restrict__ gsum)
{
    __shared__ float sacc[8][DIM];
    __shared__ int   sbatch[8];
    int wid  = threadIdx.x >> 5;
    int lane = threadIdx.x & 31;
    int node = blockIdx.x * 8 + wid;
    bool valid = node < N_NODES;

    float4 acc = make_float4(0.f, 0.f, 0.f, 0.f);
    int g = -1;
    if (valid) {
        float aDn   = aD[node];
        float selfv = leaky(aS[node] + aDn);
        int beg = off[node], end = off[node + 1];

        float m = selfv;
        for (int i = beg + lane; i < end; i += 32)
            m = fmaxf(m, leaky(aS[src[eid[i]]] + aDn));
#pragma unroll
        for (int d = 16; d; d >>= 1)
            m = fmaxf(m, __shfl_xor_sync(0xffffffff, m, d));

        float den = __expf(selfv - m);
        float4 hv = ((const float4*)H)[(long)node * 32 + lane];
        acc = make_float4(hv.x * den, hv.y * den, hv.z * den, hv.w * den);

        for (int i = beg; i < end; i++) {
            int s = src[eid[i]];
            float ex = __expf(leaky(aS[s] + aDn) - m);   // same across lanes
            den += ex;
            float4 hs = ((const float4*)H)[(long)s * 32 + lane];
            acc.x = fmaf(hs.x, ex, acc.x);
            acc.y = fmaf(hs.y, ex, acc.y);
            acc.z = fmaf(hs.z, ex, acc.z);
            acc.w = fmaf(hs.w, ex, acc.w);
        }
        float inv = 1.f / den;
        acc.x *= inv; acc.y *= inv; acc.z *= inv; acc.w *= inv;
        g = batch[node];
    }
    if (lane == 0) sbatch[wid] = g;
    ((float4*)sacc[wid])[lane] = acc;
    __syncthreads();

    int g0 = sbatch[0];
    bool uniform = (g0 >= 0);
#pragma unroll
    for (int w = 1; w < 8; w++) uniform &= (sbatch[w] == g0);

    if (uniform) {
        if (threadIdx.x < DIM) {
            float v = 0.f;
#pragma unroll
            for (int w = 0; w < 8; w++) v += sacc[w][threadIdx.x];
            atomicAdd(&gsum[(long)g0 * DIM + threadIdx.x], v);
        }
    } else if (valid) {
        float* dp = &gsum[(long)g * DIM + lane * 4];
        atomicAdd(dp + 0, acc.x);
        atomicAdd(dp + 1, acc.y);
        atomicAdd(dp + 2, acc.z);
        atomicAdd(dp + 3, acc.w);
    }
}

// ---------------- pool counts (smem histogram) -------------------------------
__global__ void pool_cnt_hist(const int* __restrict__ batch, float* __restrict__ gcnt)
{
    __shared__ int hist[GRAPHS];
    int t = threadIdx.x;
    if (t < GRAPHS) hist[t] = 0;
    __syncthreads();
    int i = blockIdx.x * blockDim.x + t;
    if (i < N_NODES) atomicAdd(&hist[batch[i]], 1);
    __syncthreads();
    if (t < GRAPHS && hist[t] > 0) atomicAdd(&gcnt[t], (float)hist[t]);
}

// ---------------- classifier MLP ---------------------------------------------
__global__ void classifier(const float* __restrict__ gsum, const float* __restrict__ gcnt,
                           const float* __restrict__ b2,
                           const float* __restrict__ Wc1, const float* __restrict__ bc1,
                           const float* __restrict__ Wc2, const float* __restrict__ bc2,
                           float* __restrict__ out)
{
    __shared__ float emb[DIM];
    __shared__ float z[64];
    int g = blockIdx.x, t = threadIdx.x;
    float cnt = fmaxf(gcnt[g], 1.f);
    emb[t] = gsum[(long)g * DIM + t] / cnt + b2[t];
    __syncthreads();
    if (t < 64) {
        float a = bc1[t];
#pragma unroll 8
        for (int k = 0; k < DIM; k++) a = fmaf(emb[k], Wc1[k * 64 + t], a);
        z[t] = a > 0.f ? a : expm1f(a);
    }
    __syncthreads();
    if (t < NCLASS) {
        float a = bc2[t];
#pragma unroll
        for (int k = 0; k < 64; k++) a = fmaf(z[k], Wc2[k * NCLASS + t], a);
        out[(long)g * NCLASS + t] = a;
    }
}

// ---------------- launch ------------------------------------------------------
extern "C" void kernel_launch(void* const* d_in, const int* in_sizes, int n_in,
                              void* d_out, int out_size)
{
    const float* x        = (const float*)d_in[0];
    const int*   esrc     = (const int*)  d_in[1];
    const int*   edst     = (const int*)  d_in[2];
    const int*   batch    = (const int*)  d_in[3];
    const float* W1       = (const float*)d_in[4];
    const float* b1       = (const float*)d_in[5];
    const float* att_src1 = (const float*)d_in[6];
    const float* att_dst1 = (const float*)d_in[7];
    const float* W2       = (const float*)d_in[8];
    const float* b2       = (const float*)d_in[9];
    const float* att_src2 = (const float*)d_in[10];
    const float* att_dst2 = (const float*)d_in[11];
    const float* bn_g     = (const float*)d_in[12];
    const float* bn_b     = (const float*)d_in[13];
    const float* bn_m     = (const float*)d_in[14];
    const float* bn_v     = (const float*)d_in[15];
    const float* Wc1      = (const float*)d_in[16];
    const float* bc1      = (const float*)d_in[17];
    const float* Wc2      = (const float*)d_in[18];
    const float* bc2      = (const float*)d_in[19];
    float* out = (float*)d_out;

    float *p_h, *p_mid, *p_as, *p_ad, *p_gsum, *p_gcnt;
    int *p_deg, *p_off, *p_cur, *p_eid;
    cudaGetSymbolAddress((void**)&p_h,    g_h);
    cudaGetSymbolAddress((void**)&p_mid,  g_mid);
    cudaGetSymbolAddress((void**)&p_as,   g_asrc);
    cudaGetSymbolAddress((void**)&p_ad,   g_adst);
    cudaGetSymbolAddress((void**)&p_deg,  g_deg);
    cudaGetSymbolAddress((void**)&p_off,  g_off);
    cudaGetSymbolAddress((void**)&p_cur,  g_cur);
    cudaGetSymbolAddress((void**)&p_eid,  g_eid);
    cudaGetSymbolAddress((void**)&p_gsum, g_gsum);
    cudaGetSymbolAddress((void**)&p_gcnt, g_gcnt);

    const int TB = 256;
    int node_blocks = (N_NODES + TB - 1) / TB;
    int edge_blocks = (N_EDGES + TB - 1) / TB;
    int gemm_blocks = (N_NODES + 3) / 4;
    int agg_blocks  = (N_NODES + 7) / 8;

    // CSR build (per-launch; depends only on edge_dst)
    zero_all<<<node_blocks, TB>>>(p_deg, p_gsum, p_gcnt);
    hist_dst<<<edge_blocks, TB>>>(edst, p_deg);
    scan_deg<<<1, 1024>>>(p_deg, p_off, p_cur);
    scatter_edges<<<edge_blocks, TB>>>(edst, p_cur, p_eid);

    // layer 1
    gemm_alpha_kernel<<<gemm_blocks, 128>>>(x, W1, att_src1, att_dst1, p_h, p_as, p_ad, HEADS);
    agg_layer1<<<agg_blocks, TB>>>(p_eid, p_off, esrc, p_as, p_ad, p_h,
                                   b1, bn_g, bn_b, bn_m, bn_v, p_mid);

    // layer 2
    gemm_alpha_kernel<<<gemm_blocks, 128>>>(p_mid, W2, att_src2, att_dst2, p_h, p_as, p_ad, 1);
    agg_layer2<<<agg_blocks, TB>>>(p_eid, p_off, esrc, p_as, p_ad, p_h, batch, p_gsum);

    // pool counts + classifier
    pool_cnt_hist<<<node_blocks, TB>>>(batch, p_gcnt);
    classifier<<<GRAPHS, DIM>>>(p_gsum, p_gcnt, b2, Wc1, bc1, Wc2, bc2, out);
}